// round 8
// baseline (speedup 1.0000x reference)
#include <cuda_runtime.h>
#include <cuda_bf16.h>
#include <cuda_fp8.h>
#include <cstdint>

// ---------------------------------------------------------------------------
// mLSTM single step, B=8192, V=50257, E=1024, H=2048, O=2
//   x   = emb[inp]
//   m_t = (x@W_mx^T + b_mx) * (h0@W_mh^T + b_mh)            [bf16 HMMA]
//   ct  = tanh(x@W_cx^T + m_t@W_cm^T + b)                   [bf16 HMMA]  (accuracy-critical)
//   f,i,o = sigmoid(x@W_zx^T + m_t@W_zm^T + b)              [fp8 e4m3 QMMA]
//   cx  = f*c0 + i*ct ; hx = o*tanh(cx) ; out = hx@W_dec^T + b_dec
// d_out: [ out(B,2) | hx(B,H) | cx(B,H) ]  fp32
//
// FP8 scaling (exact powers of 2): x*64, W*64, m_t*256.
// acc = x-part in 2^12 units; boundary acc*=4 -> 2^14; dequant 2^-14.
// ---------------------------------------------------------------------------

#define B_  8192
#define E_  1024
#define H_  2048
#define MEG (1 << 20)

__device__ __align__(16) __nv_bfloat16 g_xb [(size_t)B_ * E_];   // 16 MB bf16 x
__device__ __align__(16) __nv_bfloat16 g_h0b[(size_t)B_ * H_];   // 32 MB bf16 h0
__device__ __align__(16) __nv_bfloat16 g_mtb[(size_t)B_ * H_];   // 32 MB bf16 m_t
__device__ __align__(16) __nv_bfloat16 g_wbf[(size_t)12 * MEG];  // 24 MB bf16 W_mx,W_mh,W_cx,W_cm
__device__ __align__(16) float         g_ct [(size_t)B_ * H_];   // 64 MB fp32 c~
__device__ __align__(16) uint8_t       g_x8 [(size_t)B_ * E_];   //  8 MB fp8 x*64
__device__ __align__(16) uint8_t       g_mt8[(size_t)B_ * H_];   // 16 MB fp8 m_t*256
__device__ __align__(16) uint8_t       g_w8 [(size_t)18 * MEG];  // 18 MB fp8 f,i,o weights*64

#define OFF_MX 0                  // bf16, H x E
#define OFF_MH (2 * MEG)          // bf16, H x H
#define OFF_CX (6 * MEG)          // bf16, H x E
#define OFF_CM (8 * MEG)          // bf16, H x H
#define OFF8_ZX(z) ((size_t)(z) * 6 * MEG)            // fp8: z 0=f 1=i 2=o (H x E)
#define OFF8_ZM(z) ((size_t)(z) * 6 * MEG + 2 * MEG)  //                   (H x H)

// ---------------------------------------------------------------------------
// helpers
// ---------------------------------------------------------------------------
__device__ __forceinline__ uint32_t smem_u32(const void* p) {
    uint32_t a;
    asm("{ .reg .u64 t; cvta.to.shared.u64 t, %1; cvt.u32.u64 %0, t; }"
        : "=r"(a) : "l"(p));
    return a;
}
__device__ __forceinline__ void cpa16(uint32_t dst, const void* src) {
    asm volatile("cp.async.cg.shared.global [%0], [%1], 16;\n" :: "r"(dst), "l"(src));
}
__device__ __forceinline__ void cp_commit() { asm volatile("cp.async.commit_group;\n" ::); }
template <int N> __device__ __forceinline__ void cp_wait() {
    asm volatile("cp.async.wait_group %0;\n" :: "n"(N));
}
__device__ __forceinline__ void ldsm4(uint32_t& r0, uint32_t& r1, uint32_t& r2,
                                      uint32_t& r3, uint32_t addr) {
    asm volatile("ldmatrix.sync.aligned.m8n8.x4.shared.b16 {%0,%1,%2,%3}, [%4];"
                 : "=r"(r0), "=r"(r1), "=r"(r2), "=r"(r3) : "r"(addr));
}
__device__ __forceinline__ void mma16816(float c[4], const uint32_t a[4], const uint32_t b[2]) {
    asm volatile(
        "mma.sync.aligned.m16n8k16.row.col.f32.bf16.bf16.f32 "
        "{%0,%1,%2,%3}, {%4,%5,%6,%7}, {%8,%9}, {%0,%1,%2,%3};\n"
        : "+f"(c[0]), "+f"(c[1]), "+f"(c[2]), "+f"(c[3])
        : "r"(a[0]), "r"(a[1]), "r"(a[2]), "r"(a[3]), "r"(b[0]), "r"(b[1]));
}
__device__ __forceinline__ void mma_fp8(float c[4], const uint32_t a[4], const uint32_t b[2]) {
    asm volatile(
        "mma.sync.aligned.m16n8k32.row.col.f32.e4m3.e4m3.f32 "
        "{%0,%1,%2,%3}, {%4,%5,%6,%7}, {%8,%9}, {%0,%1,%2,%3};\n"
        : "+f"(c[0]), "+f"(c[1]), "+f"(c[2]), "+f"(c[3])
        : "r"(a[0]), "r"(a[1]), "r"(a[2]), "r"(a[3]), "r"(b[0]), "r"(b[1]));
}
// pack (v0 -> low byte, v1 -> high byte)
__device__ __forceinline__ uint16_t fp8pair(float v0, float v1) {
    uint16_t r;
    asm("cvt.rn.satfinite.e4m3x2.f32 %0, %1, %2;" : "=h"(r) : "f"(v1), "f"(v0));
    return r;
}
__device__ __forceinline__ float sigf(float v)   { return 1.f / (1.f + __expf(-v)); }
__device__ __forceinline__ float tanhf_(float v) { return fmaf(2.f, 1.f / (1.f + __expf(-2.f * v)), -1.f); }

// ---------------------------------------------------------------------------
// conversions
// ---------------------------------------------------------------------------
struct Cvt5 { const float* s[5]; __nv_bfloat16* d[5]; int n4[5]; };

__global__ void cvt_f32_bf16(Cvt5 a) {
    const int seg = blockIdx.y;
    const float4* __restrict__ s = (const float4*)a.s[seg];
    uint2* __restrict__ d = (uint2*)a.d[seg];
    const int n4 = a.n4[seg];
    for (int i = blockIdx.x * blockDim.x + threadIdx.x; i < n4;
         i += gridDim.x * blockDim.x) {
        float4 v = s[i];
        __nv_bfloat162 lo = __float22bfloat162_rn(make_float2(v.x, v.y));
        __nv_bfloat162 hi = __float22bfloat162_rn(make_float2(v.z, v.w));
        uint2 o; o.x = *(unsigned*)&lo; o.y = *(unsigned*)&hi;
        d[i] = o;
    }
}

struct Cvt6 { const float* s[6]; uint8_t* d[6]; int n4[6]; };

__global__ void cvt_f32_fp8(Cvt6 a) {
    const int seg = blockIdx.y;
    const float4* __restrict__ s = (const float4*)a.s[seg];
    uint32_t* __restrict__ d = (uint32_t*)a.d[seg];
    const int n4 = a.n4[seg];
    for (int i = blockIdx.x * blockDim.x + threadIdx.x; i < n4;
         i += gridDim.x * blockDim.x) {
        float4 v = s[i];
        uint32_t lo = fp8pair(v.x * 64.f, v.y * 64.f);
        uint32_t hi = fp8pair(v.z * 64.f, v.w * 64.f);
        d[i] = lo | (hi << 16);
    }
}

// x = emb[inp] -> bf16 + fp8*64
__global__ void gather_x(const int* __restrict__ inp, const float* __restrict__ emb) {
    const int b = blockIdx.x;
    const int v = inp[b];
    float4 t = ((const float4*)(emb + (size_t)v * E_))[threadIdx.x];
    __nv_bfloat162 lo = __float22bfloat162_rn(make_float2(t.x, t.y));
    __nv_bfloat162 hi = __float22bfloat162_rn(make_float2(t.z, t.w));
    uint2 o; o.x = *(unsigned*)&lo; o.y = *(unsigned*)&hi;
    ((uint2*)(g_xb + (size_t)b * E_))[threadIdx.x] = o;
    uint32_t l8 = fp8pair(t.x * 64.f, t.y * 64.f);
    uint32_t h8 = fp8pair(t.z * 64.f, t.w * 64.f);
    ((uint32_t*)(g_x8 + (size_t)b * E_))[threadIdx.x] = l8 | (h8 << 16);
}

// ---------------------------------------------------------------------------
// bf16 GEMM geometry: BM=128, BN=64, BK=32, 512 thr (16 warps 4x4), ldmatrix
// ---------------------------------------------------------------------------
#define LDS_  40
#define NT_X  32
#define NT_TOT 96

// m_t kernel: dual accumulators; epilogue m_t=(ax+b)(ah+b) -> bf16 + fp8*256
__global__ __launch_bounds__(512, 1)
void gemm_mt(const float* __restrict__ b_mx, const float* __restrict__ b_mh) {
    __shared__ __align__(16) __nv_bfloat16 As[2][128 * LDS_];
    __shared__ __align__(16) __nv_bfloat16 Bs[2][64 * LDS_];
    __shared__ float bs[2][64];

    const int m0 = blockIdx.y * 128;
    const int n0 = blockIdx.x * 64;
    const int tid = threadIdx.x, lane = tid & 31, warp = tid >> 5;
    const int wm = warp & 3, wn = warp >> 2;
    const int g = lane >> 2, ti = lane & 3;
    const int l16 = lane & 15, kh = lane >> 4;

    if (tid < 64) {
        bs[0][tid] = b_mx[n0 + tid];
        bs[1][tid] = b_mh[n0 + tid];
    }

    float ax[2][2][4], ah[2][2][4];
#pragma unroll
    for (int mt = 0; mt < 2; mt++)
#pragma unroll
        for (int nt = 0; nt < 2; nt++)
#pragma unroll
            for (int j = 0; j < 4; j++) { ax[mt][nt][j] = 0.f; ah[mt][nt][j] = 0.f; }

    auto issue = [&](int t, int s) {
        const __nv_bfloat16 *Ab, *Wb; int ld; int tt = t;
        if (t < NT_X) { Ab = g_xb;  Wb = g_wbf + OFF_MX; ld = E_; }
        else          { Ab = g_h0b; Wb = g_wbf + OFF_MH; ld = H_; tt = t - NT_X; }
        const int k0 = tt * 32;
        {
            int r = tid >> 2, c = tid & 3;
            cpa16(smem_u32(&As[s][r * LDS_ + c * 8]),
                  Ab + (size_t)(m0 + r) * ld + k0 + c * 8);
        }
        if (tid < 256) {
            int r = tid >> 2, c = tid & 3;
            cpa16(smem_u32(&Bs[s][r * LDS_ + c * 8]),
                  Wb + (size_t)(n0 + r) * ld + k0 + c * 8);
        }
        cp_commit();
    };

    issue(0, 0);
    for (int t = 0; t < NT_TOT; t++) {
        if (t + 1 < NT_TOT) { issue(t + 1, (t + 1) & 1); cp_wait<1>(); }
        else                { cp_wait<0>(); }
        __syncthreads();
        const int st = t & 1;
        const bool px = (t < NT_X);
#pragma unroll
        for (int ks = 0; ks < 2; ks++) {
            const int kb = ks * 16;
            uint32_t af[2][4];
#pragma unroll
            for (int mt = 0; mt < 2; mt++)
                ldsm4(af[mt][0], af[mt][1], af[mt][2], af[mt][3],
                      smem_u32(&As[st][(wm * 32 + mt * 16 + l16) * LDS_ + kb + kh * 8]));
            uint32_t r0, r1, r2, r3;
            ldsm4(r0, r1, r2, r3,
                  smem_u32(&Bs[st][(wn * 16 + l16) * LDS_ + kb + kh * 8]));
            uint32_t b0[2] = {r0, r2}, b1[2] = {r1, r3};
            if (px) {
#pragma unroll
                for (int mt = 0; mt < 2; mt++) {
                    mma16816(ax[mt][0], af[mt], b0);
                    mma16816(ax[mt][1], af[mt], b1);
                }
            } else {
#pragma unroll
                for (int mt = 0; mt < 2; mt++) {
                    mma16816(ah[mt][0], af[mt], b0);
                    mma16816(ah[mt][1], af[mt], b1);
                }
            }
        }
        __syncthreads();
    }

#pragma unroll
    for (int mt = 0; mt < 2; mt++)
#pragma unroll
        for (int nt = 0; nt < 2; nt++) {
            const int nl = wn * 16 + nt * 8 + ti * 2;
            const int n = n0 + nl;
#pragma unroll
            for (int h = 0; h < 2; h++) {
                const int m = m0 + wm * 32 + mt * 16 + g + h * 8;
                float v0 = (ax[mt][nt][h * 2 + 0] + bs[0][nl + 0]) *
                           (ah[mt][nt][h * 2 + 0] + bs[1][nl + 0]);
                float v1 = (ax[mt][nt][h * 2 + 1] + bs[0][nl + 1]) *
                           (ah[mt][nt][h * 2 + 1] + bs[1][nl + 1]);
                __nv_bfloat162 p = __float22bfloat162_rn(make_float2(v0, v1));
                *(unsigned*)(g_mtb + (size_t)m * H_ + n) = *(unsigned*)&p;
                *(uint16_t*)(g_mt8 + (size_t)m * H_ + n) =
                    fp8pair(v0 * 256.f, v1 * 256.f);
            }
        }
}

// c-gate kernel (bf16, accuracy-critical): ct = tanh(x@Wcx + m_t@Wcm + b) -> fp32
__global__ __launch_bounds__(512, 1)
void gemm_c(const float* __restrict__ bcx, const float* __restrict__ bcm) {
    __shared__ __align__(16) __nv_bfloat16 As[2][128 * LDS_];
    __shared__ __align__(16) __nv_bfloat16 Bs[2][64 * LDS_];
    __shared__ float bs[64];

    const int m0 = blockIdx.y * 128;
    const int n0 = blockIdx.x * 64;
    const int tid = threadIdx.x, lane = tid & 31, warp = tid >> 5;
    const int wm = warp & 3, wn = warp >> 2;
    const int g = lane >> 2, ti = lane & 3;
    const int l16 = lane & 15, kh = lane >> 4;

    if (tid < 64) bs[tid] = bcx[n0 + tid] + bcm[n0 + tid];

    float acc[2][2][4];
#pragma unroll
    for (int mt = 0; mt < 2; mt++)
#pragma unroll
        for (int nt = 0; nt < 2; nt++)
#pragma unroll
            for (int j = 0; j < 4; j++) acc[mt][nt][j] = 0.f;

    auto issue = [&](int t, int s) {
        const __nv_bfloat16 *Ab, *Wb; int ld; int tt = t;
        if (t < NT_X) { Ab = g_xb;  Wb = g_wbf + OFF_CX; ld = E_; }
        else          { Ab = g_mtb; Wb = g_wbf + OFF_CM; ld = H_; tt = t - NT_X; }
        const int k0 = tt * 32;
        {
            int r = tid >> 2, c = tid & 3;
            cpa16(smem_u32(&As[s][r * LDS_ + c * 8]),
                  Ab + (size_t)(m0 + r) * ld + k0 + c * 8);
        }
        if (tid < 256) {
            int r = tid >> 2, c = tid & 3;
            cpa16(smem_u32(&Bs[s][r * LDS_ + c * 8]),
                  Wb + (size_t)(n0 + r) * ld + k0 + c * 8);
        }
        cp_commit();
    };

    issue(0, 0);
    for (int t = 0; t < NT_TOT; t++) {
        if (t + 1 < NT_TOT) { issue(t + 1, (t + 1) & 1); cp_wait<1>(); }
        else                { cp_wait<0>(); }
        __syncthreads();
        const int st = t & 1;
#pragma unroll
        for (int ks = 0; ks < 2; ks++) {
            const int kb = ks * 16;
            uint32_t af[2][4];
#pragma unroll
            for (int mt = 0; mt < 2; mt++)
                ldsm4(af[mt][0], af[mt][1], af[mt][2], af[mt][3],
                      smem_u32(&As[st][(wm * 32 + mt * 16 + l16) * LDS_ + kb + kh * 8]));
            uint32_t r0, r1, r2, r3;
            ldsm4(r0, r1, r2, r3,
                  smem_u32(&Bs[st][(wn * 16 + l16) * LDS_ + kb + kh * 8]));
            uint32_t b0[2] = {r0, r2}, b1[2] = {r1, r3};
#pragma unroll
            for (int mt = 0; mt < 2; mt++) {
                mma16816(acc[mt][0], af[mt], b0);
                mma16816(acc[mt][1], af[mt], b1);
            }
        }
        __syncthreads();
    }

#pragma unroll
    for (int mt = 0; mt < 2; mt++)
#pragma unroll
        for (int nt = 0; nt < 2; nt++) {
            const int nl = wn * 16 + nt * 8 + ti * 2;
            const int n = n0 + nl;
#pragma unroll
            for (int h = 0; h < 2; h++) {
                const int m = m0 + wm * 32 + mt * 16 + g + h * 8;
                float2 v;
                v.x = tanhf_(acc[mt][nt][h * 2 + 0] + bs[nl + 0]);
                v.y = tanhf_(acc[mt][nt][h * 2 + 1] + bs[nl + 1]);
                *(float2*)(g_ct + (size_t)m * H_ + n) = v;
            }
        }
}

// ---------------------------------------------------------------------------
// f,i,o kernel (fp8 QMMA): BM=128, BN=64, BK=128B, 512 thr, 3 gates fused,
// 3-stage cp.async pipeline; rows 144B stride (conflict-free ldmatrix).
// ---------------------------------------------------------------------------
#define LDSF   144
#define GK_AS  18432            // 128*144
#define GK_BS  9216             // 64*144
#define GK_STG (GK_AS + 3 * GK_BS)   // 46080
#define GK_SMEM (3 * GK_STG + 1024)  // 139264
#define GK_NT  24
#define GK_NX  8

__global__ __launch_bounds__(512, 1)
void gemm_fio(const float* __restrict__ bfx, const float* __restrict__ bfm,
              const float* __restrict__ bix, const float* __restrict__ bim,
              const float* __restrict__ box_, const float* __restrict__ bom,
              const float* __restrict__ c0,
              float* __restrict__ hx, float* __restrict__ cx) {
    extern __shared__ __align__(16) char sm[];
    const uint32_t smb = smem_u32(sm);
    float* bs = (float*)(sm + 3 * GK_STG);

    const int m0 = blockIdx.y * 128;
    const int n0 = blockIdx.x * 64;
    const int tid = threadIdx.x, lane = tid & 31, warp = tid >> 5;
    const int wm = warp & 3, wn = warp >> 2;
    const int g = lane >> 2, ti = lane & 3;
    const int l16 = lane & 15, kh = lane >> 4;

    if (tid < 64) {
        const int n = n0 + tid;
        bs[0 * 64 + tid] = bfx[n] + bfm[n];
        bs[1 * 64 + tid] = bix[n] + bim[n];
        bs[2 * 64 + tid] = box_[n] + bom[n];
    }

    float acc[3][2][2][4];
#pragma unroll
    for (int z = 0; z < 3; z++)
#pragma unroll
        for (int mt = 0; mt < 2; mt++)
#pragma unroll
            for (int nt = 0; nt < 2; nt++)
#pragma unroll
                for (int j = 0; j < 4; j++) acc[z][mt][nt][j] = 0.f;

    auto issue = [&](int t, int s) {
        const bool xph = (t < GK_NX);
        const uint8_t* Ab = xph ? g_x8 : g_mt8;
        const int ld = xph ? E_ : H_;
        const int k0 = (xph ? t : t - GK_NX) * 128;
        const uint32_t base = smb + s * GK_STG;
#pragma unroll
        for (int i = 0; i < 2; i++) {        // A: 128 rows x 8 chunks
            int lin = tid + i * 512, r = lin >> 3, c = lin & 7;
            cpa16(base + r * LDSF + c * 16,
                  Ab + (size_t)(m0 + r) * ld + k0 + c * 16);
        }
#pragma unroll
        for (int i = 0; i < 3; i++) {        // B: 3 x 64 rows x 8 chunks
            int lin = tid + i * 512;
            int z = lin >> 9, rr = (lin >> 3) & 63, cc = lin & 7;
            const uint8_t* Wb = g_w8 + (xph ? OFF8_ZX(z) : OFF8_ZM(z));
            cpa16(base + GK_AS + z * GK_BS + rr * LDSF + cc * 16,
                  Wb + (size_t)(n0 + rr) * ld + k0 + cc * 16);
        }
        cp_commit();
    };

    issue(0, 0); issue(1, 1);
    for (int t = 0; t < GK_NT; t++) {
        if (t + 2 < GK_NT) { issue(t + 2, (t + 2) % 3); cp_wait<2>(); }
        else if (t + 1 < GK_NT) cp_wait<1>();
        else cp_wait<0>();
        __syncthreads();

        if (t == GK_NX) {   // phase boundary: 2^12 basis -> 2^14 basis
#pragma unroll
            for (int z = 0; z < 3; z++)
#pragma unroll
                for (int mt = 0; mt < 2; mt++)
#pragma unroll
                    for (int nt = 0; nt < 2; nt++)
#pragma unroll
                        for (int j = 0; j < 4; j++) acc[z][mt][nt][j] *= 4.f;
        }

        const uint32_t base = smb + (t % 3) * GK_STG;
#pragma unroll
        for (int ks = 0; ks < 4; ks++) {
            const int kb = ks * 32;
            uint32_t af[2][4];
#pragma unroll
            for (int mt = 0; mt < 2; mt++)
                ldsm4(af[mt][0], af[mt][1], af[mt][2], af[mt][3],
                      base + (wm * 32 + mt * 16 + l16) * LDSF + kb + kh * 16);
#pragma unroll
            for (int z = 0; z < 3; z++) {
                uint32_t r0, r1, r2, r3;
                ldsm4(r0, r1, r2, r3,
                      base + GK_AS + z * GK_BS + (wn * 16 + l16) * LDSF + kb + kh * 16);
                uint32_t b0[2] = {r0, r2}, b1[2] = {r1, r3};
#pragma unroll
                for (int mt = 0; mt < 2; mt++) {
                    mma_fp8(acc[z][mt][0], af[mt], b0);
                    mma_fp8(acc[z][mt][1], af[mt], b1);
                }
            }
        }
        __syncthreads();
    }

    // epilogue: dequant, sigmoids, combine with ct (fp32) and c0
    constexpr float DQ = 1.f / 16384.f;
#pragma unroll
    for (int mt = 0; mt < 2; mt++)
#pragma unroll
        for (int nt = 0; nt < 2; nt++) {
            const int nl = wn * 16 + nt * 8 + ti * 2;
            const int n = n0 + nl;
#pragma unroll
            for (int h = 0; h < 2; h++) {
                const int m = m0 + wm * 32 + mt * 16 + g + h * 8;
                float2 c0v = *(const float2*)(c0 + (size_t)m * H_ + n);
                float2 ctv = *(const float2*)(g_ct + (size_t)m * H_ + n);
                float2 hv, cvv;
#pragma unroll
                for (int j = 0; j < 2; j++) {
                    const int e = h * 2 + j;
                    float fg = sigf(acc[0][mt][nt][e] * DQ + bs[0 * 64 + nl + j]);
                    float ig = sigf(acc[1][mt][nt][e] * DQ + bs[1 * 64 + nl + j]);
                    float og = sigf(acc[2][mt][nt][e] * DQ + bs[2 * 64 + nl + j]);
                    float ct  = j ? ctv.y : ctv.x;
                    float c0e = j ? c0v.y : c0v.x;
                    float cv = fg * c0e + ig * ct;
                    ((float*)&cvv)[j] = cv;
                    ((float*)&hv)[j]  = og * tanhf_(cv);
                }
                *(float2*)(cx + (size_t)m * H_ + n) = cvv;
                *(float2*)(hx + (size_t)m * H_ + n) = hv;
            }
        }
}

// ---------------------------------------------------------------------------
// decoder: out[b,0:2] = hx[b]@W_dec^T + b_dec   (warp per row)
// ---------------------------------------------------------------------------
__global__ void decoder(const float* __restrict__ hx, const float* __restrict__ Wd,
                        const float* __restrict__ bd, float* __restrict__ out) {
    const int gw = (blockIdx.x * blockDim.x + threadIdx.x) >> 5;
    const int lane = threadIdx.x & 31;
    if (gw >= B_) return;
    const float4* h4 = (const float4*)(hx + (size_t)gw * H_);
    const float4* w0 = (const float4*)(Wd);
    const float4* w1 = (const float4*)(Wd + H_);
    float s0 = 0.f, s1 = 0.f;
    for (int i = lane; i < H_ / 4; i += 32) {
        float4 h = h4[i], a = w0[i], b = w1[i];
        s0 += h.x * a.x + h.y * a.y + h.z * a.z + h.w * a.w;
        s1 += h.x * b.x + h.y * b.y + h.z * b.z + h.w * b.w;
    }
#pragma unroll
    for (int o = 16; o; o >>= 1) {
        s0 += __shfl_xor_sync(0xFFFFFFFFu, s0, o);
        s1 += __shfl_xor_sync(0xFFFFFFFFu, s1, o);
    }
    if (lane == 0) {
        out[(size_t)gw * 2 + 0] = s0 + bd[0];
        out[(size_t)gw * 2 + 1] = s1 + bd[1];
    }
}

// ---------------------------------------------------------------------------
extern "C" void kernel_launch(void* const* d_in, const int* in_sizes, int n_in,
                              void* d_out, int out_size) {
    const int*   inp  = (const int*)  d_in[0];
    const float* h0   = (const float*)d_in[1];
    const float* c0   = (const float*)d_in[2];
    const float* emb  = (const float*)d_in[3];
    const float *W_mx = (const float*)d_in[4],  *b_mx = (const float*)d_in[5];
    const float *W_mh = (const float*)d_in[6],  *b_mh = (const float*)d_in[7];
    const float *W_fx = (const float*)d_in[8],  *b_fx = (const float*)d_in[9];
    const float *W_fm = (const float*)d_in[10], *b_fm = (const float*)d_in[11];
    const float *W_ix = (const float*)d_in[12], *b_ix = (const float*)d_in[13];
    const float *W_im = (const float*)d_in[14], *b_im = (const float*)d_in[15];
    const float *W_ox = (const float*)d_in[16], *b_ox = (const float*)d_in[17];
    const float *W_om = (const float*)d_in[18], *b_om = (const float*)d_in[19];
    const float *W_cx = (const float*)d_in[20], *b_cx = (const float*)d_in[21];
    const float *W_cm = (const float*)d_in[22], *b_cm = (const float*)d_in[23];
    const float *W_dec= (const float*)d_in[24], *b_dec= (const float*)d_in[25];
    float* out = (float*)d_out;

    __nv_bfloat16 *wbf, *h0b;
    uint8_t *w8;
    cudaGetSymbolAddress((void**)&wbf, g_wbf);
    cudaGetSymbolAddress((void**)&h0b, g_h0b);
    cudaGetSymbolAddress((void**)&w8,  g_w8);

    // 1) bf16 conversions: W_mx, W_mh, W_cx, W_cm, h0
    Cvt5 c5;
    c5.s[0] = W_mx; c5.d[0] = wbf + OFF_MX; c5.n4[0] = 2 * MEG / 4;
    c5.s[1] = W_mh; c5.d[1] = wbf + OFF_MH; c5.n4[1] = 4 * MEG / 4;
    c5.s[2] = W_cx; c5.d[2] = wbf + OFF_CX; c5.n4[2] = 2 * MEG / 4;
    c5.s[3] = W_cm; c5.d[3] = wbf + OFF_CM; c5.n4[3] = 4 * MEG / 4;
    c5.s[4] = h0;   c5.d[4] = h0b;          c5.n4[4] = 16 * MEG / 4;
    cvt_f32_bf16<<<dim3(1024, 5), 256>>>(c5);

    // 2) fp8 conversions (*64): f,i,o weights
    Cvt6 c6;
    const float* gs[6] = {W_fx, W_fm, W_ix, W_im, W_ox, W_om};
    for (int z = 0; z < 3; z++) {
        c6.s[2*z]   = gs[2*z];   c6.d[2*z]   = w8 + OFF8_ZX(z); c6.n4[2*z]   = 2 * MEG / 4;
        c6.s[2*z+1] = gs[2*z+1]; c6.d[2*z+1] = w8 + OFF8_ZM(z); c6.n4[2*z+1] = 4 * MEG / 4;
    }
    cvt_f32_fp8<<<dim3(1024, 6), 256>>>(c6);

    // 3) x = emb[inp] -> bf16 + fp8
    gather_x<<<B_, 256>>>(inp, emb);

    // 4) m_t (bf16 GEMM) -> bf16 + fp8
    gemm_mt<<<dim3(H_ / 64, B_ / 128), 512>>>(b_mx, b_mh);

    // 5) ct (bf16 GEMM, accuracy-critical) -> fp32
    gemm_c<<<dim3(H_ / 64, B_ / 128), 512>>>(b_cx, b_cm);

    // 6) f,i,o (fp8 GEMM) + cx/hx fused, into d_out
    float* hx_out = out + 2 * (size_t)B_;
    float* cx_out = hx_out + (size_t)B_ * H_;
    cudaFuncSetAttribute(gemm_fio, cudaFuncAttributeMaxDynamicSharedMemorySize,
                         GK_SMEM);
    gemm_fio<<<dim3(H_ / 64, B_ / 128), 512, GK_SMEM>>>(
        b_fx, b_fm, b_ix, b_im, b_ox, b_om, c0, hx_out, cx_out);

    // 7) out = hx@W_dec^T + b_dec
    decoder<<<(B_ * 32) / 256, 256>>>(hx_out, W_dec, b_dec, out);
}

// round 9
// speedup vs baseline: 1.3530x; 1.3530x over previous
#include <cuda_runtime.h>
#include <cuda_bf16.h>
#include <cuda_fp8.h>
#include <cstdint>

// ---------------------------------------------------------------------------
// mLSTM single step, B=8192, V=50257, E=1024, H=2048, O=2
//   x   = emb[inp]
//   m_t = (x@W_mx^T + b_mx) * (h0@W_mh^T + b_mh)            [bf16 HMMA]
//   ct  = tanh(x@W_cx^T + m_t@W_cm^T + b)                   [bf16 HMMA]
//   f,i,o = sigmoid(x@W_zx^T + m_t@W_zm^T + b)              [fp8 e4m3 QMMA]
//   cx  = f*c0 + i*ct ; hx = o*tanh(cx) ; out = hx@W_dec^T + b_dec
// d_out: [ out(B,2) | hx(B,H) | cx(B,H) ]  fp32
//
// FP8 scaling (powers of 2): x*64, W*64, m_t*256; x-phase acc *=4 at boundary;
// dequant 2^-14.
// bf16 GEMMs: BM=128, BN=128, BK=64, 512 thr (16 warps 4x4, warp tile 32x32),
// 3-stage cp.async pipeline, ONE __syncthreads per k-tile.
// ---------------------------------------------------------------------------

#define B_  8192
#define E_  1024
#define H_  2048
#define MEG (1 << 20)

__device__ __align__(16) __nv_bfloat16 g_xb [(size_t)B_ * E_];   // 16 MB bf16 x
__device__ __align__(16) __nv_bfloat16 g_h0b[(size_t)B_ * H_];   // 32 MB bf16 h0
__device__ __align__(16) __nv_bfloat16 g_mtb[(size_t)B_ * H_];   // 32 MB bf16 m_t
__device__ __align__(16) __nv_bfloat16 g_wbf[(size_t)12 * MEG];  // 24 MB bf16 W_mx,W_mh,W_cx,W_cm
__device__ __align__(16) float         g_ct [(size_t)B_ * H_];   // 64 MB fp32 c~
__device__ __align__(16) uint8_t       g_x8 [(size_t)B_ * E_];   //  8 MB fp8 x*64
__device__ __align__(16) uint8_t       g_mt8[(size_t)B_ * H_];   // 16 MB fp8 m_t*256
__device__ __align__(16) uint8_t       g_w8 [(size_t)18 * MEG];  // 18 MB fp8 f,i,o W*64

#define OFF_MX 0
#define OFF_MH (2 * MEG)
#define OFF_CX (6 * MEG)
#define OFF_CM (8 * MEG)
#define OFF8_ZX(z) ((size_t)(z) * 6 * MEG)
#define OFF8_ZM(z) ((size_t)(z) * 6 * MEG + 2 * MEG)

// ---------------------------------------------------------------------------
// helpers
// ---------------------------------------------------------------------------
__device__ __forceinline__ uint32_t smem_u32(const void* p) {
    uint32_t a;
    asm("{ .reg .u64 t; cvta.to.shared.u64 t, %1; cvt.u32.u64 %0, t; }"
        : "=r"(a) : "l"(p));
    return a;
}
__device__ __forceinline__ void cpa16(uint32_t dst, const void* src) {
    asm volatile("cp.async.cg.shared.global [%0], [%1], 16;\n" :: "r"(dst), "l"(src));
}
__device__ __forceinline__ void cp_commit() { asm volatile("cp.async.commit_group;\n" ::); }
template <int N> __device__ __forceinline__ void cp_wait() {
    asm volatile("cp.async.wait_group %0;\n" :: "n"(N));
}
__device__ __forceinline__ void ldsm4(uint32_t& r0, uint32_t& r1, uint32_t& r2,
                                      uint32_t& r3, uint32_t addr) {
    asm volatile("ldmatrix.sync.aligned.m8n8.x4.shared.b16 {%0,%1,%2,%3}, [%4];"
                 : "=r"(r0), "=r"(r1), "=r"(r2), "=r"(r3) : "r"(addr));
}
__device__ __forceinline__ void mma16816(float c[4], const uint32_t a[4], const uint32_t b[2]) {
    asm volatile(
        "mma.sync.aligned.m16n8k16.row.col.f32.bf16.bf16.f32 "
        "{%0,%1,%2,%3}, {%4,%5,%6,%7}, {%8,%9}, {%0,%1,%2,%3};\n"
        : "+f"(c[0]), "+f"(c[1]), "+f"(c[2]), "+f"(c[3])
        : "r"(a[0]), "r"(a[1]), "r"(a[2]), "r"(a[3]), "r"(b[0]), "r"(b[1]));
}
__device__ __forceinline__ void mma_fp8(float c[4], const uint32_t a[4], const uint32_t b[2]) {
    asm volatile(
        "mma.sync.aligned.m16n8k32.row.col.f32.e4m3.e4m3.f32 "
        "{%0,%1,%2,%3}, {%4,%5,%6,%7}, {%8,%9}, {%0,%1,%2,%3};\n"
        : "+f"(c[0]), "+f"(c[1]), "+f"(c[2]), "+f"(c[3])
        : "r"(a[0]), "r"(a[1]), "r"(a[2]), "r"(a[3]), "r"(b[0]), "r"(b[1]));
}
__device__ __forceinline__ uint16_t fp8pair(float v0, float v1) {
    uint16_t r;
    asm("cvt.rn.satfinite.e4m3x2.f32 %0, %1, %2;" : "=h"(r) : "f"(v1), "f"(v0));
    return r;
}
__device__ __forceinline__ float sigf(float v)   { return 1.f / (1.f + __expf(-v)); }
__device__ __forceinline__ float tanhf_(float v) { return fmaf(2.f, 1.f / (1.f + __expf(-2.f * v)), -1.f); }

// ---------------------------------------------------------------------------
// conversions + gather
// ---------------------------------------------------------------------------
struct Cvt5 { const float* s[5]; __nv_bfloat16* d[5]; int n4[5]; };

__global__ void cvt_f32_bf16(Cvt5 a) {
    const int seg = blockIdx.y;
    const float4* __restrict__ s = (const float4*)a.s[seg];
    uint2* __restrict__ d = (uint2*)a.d[seg];
    const int n4 = a.n4[seg];
    for (int i = blockIdx.x * blockDim.x + threadIdx.x; i < n4;
         i += gridDim.x * blockDim.x) {
        float4 v = s[i];
        __nv_bfloat162 lo = __float22bfloat162_rn(make_float2(v.x, v.y));
        __nv_bfloat162 hi = __float22bfloat162_rn(make_float2(v.z, v.w));
        uint2 o; o.x = *(unsigned*)&lo; o.y = *(unsigned*)&hi;
        d[i] = o;
    }
}

struct Cvt6 { const float* s[6]; uint8_t* d[6]; int n4[6]; };

__global__ void cvt_f32_fp8(Cvt6 a) {
    const int seg = blockIdx.y;
    const float4* __restrict__ s = (const float4*)a.s[seg];
    uint32_t* __restrict__ d = (uint32_t*)a.d[seg];
    const int n4 = a.n4[seg];
    for (int i = blockIdx.x * blockDim.x + threadIdx.x; i < n4;
         i += gridDim.x * blockDim.x) {
        float4 v = s[i];
        uint32_t lo = fp8pair(v.x * 64.f, v.y * 64.f);
        uint32_t hi = fp8pair(v.z * 64.f, v.w * 64.f);
        d[i] = lo | (hi << 16);
    }
}

__global__ void gather_x(const int* __restrict__ inp, const float* __restrict__ emb) {
    const int b = blockIdx.x;
    const int v = inp[b];
    float4 t = ((const float4*)(emb + (size_t)v * E_))[threadIdx.x];
    __nv_bfloat162 lo = __float22bfloat162_rn(make_float2(t.x, t.y));
    __nv_bfloat162 hi = __float22bfloat162_rn(make_float2(t.z, t.w));
    uint2 o; o.x = *(unsigned*)&lo; o.y = *(unsigned*)&hi;
    ((uint2*)(g_xb + (size_t)b * E_))[threadIdx.x] = o;
    uint32_t l8 = fp8pair(t.x * 64.f, t.y * 64.f);
    uint32_t h8 = fp8pair(t.z * 64.f, t.w * 64.f);
    ((uint32_t*)(g_x8 + (size_t)b * E_))[threadIdx.x] = l8 | (h8 << 16);
}

// ---------------------------------------------------------------------------
// bf16 GEMM geometry: BM=128, BN=128, BK=64; rows 144 B (64 bf16 + 8 pad)
// 16 warps = wm(4 x 32 rows) x wn(4 x 32 cols); warp tile 32x32.
// 3 stages; per-thread per issue: 2 A + 2 B cp.async.16
// ---------------------------------------------------------------------------
#define BST    18432                 // one operand tile: 128 rows * 144 B
#define STG_B  (2 * BST)             // stage = A + B
#define BF_SMEM (3 * STG_B + 1024)   // 111616
#define NTB_X  16                    // K=1024 / 64
#define NTB    48                    // + K=2048 / 64

// m_t: dual accumulation; epilogue (ax+b)(ah+b) -> bf16 + fp8*256
__global__ __launch_bounds__(512, 1)
void gemm_mt(const float* __restrict__ b_mx, const float* __restrict__ b_mh) {
    extern __shared__ __align__(16) char sm[];
    const uint32_t smb = smem_u32(sm);
    float* bs = (float*)(sm + 3 * STG_B);

    const int m0 = blockIdx.y * 128;
    const int n0 = blockIdx.x * 128;
    const int tid = threadIdx.x, lane = tid & 31, warp = tid >> 5;
    const int wm = warp & 3, wn = warp >> 2;
    const int g = lane >> 2, ti = lane & 3;
    const int l16 = lane & 15, kh = lane >> 4;

    if (tid < 128) {
        bs[tid]       = b_mx[n0 + tid];
        bs[128 + tid] = b_mh[n0 + tid];
    }

    float ax[2][4][4], ah[2][4][4];
#pragma unroll
    for (int mt = 0; mt < 2; mt++)
#pragma unroll
        for (int q = 0; q < 4; q++)
#pragma unroll
            for (int j = 0; j < 4; j++) { ax[mt][q][j] = 0.f; ah[mt][q][j] = 0.f; }

    auto issue = [&](int t, int s) {
        const __nv_bfloat16 *Ab, *Wb; int ld; int tt = t;
        if (t < NTB_X) { Ab = g_xb;  Wb = g_wbf + OFF_MX; ld = E_; }
        else           { Ab = g_h0b; Wb = g_wbf + OFF_MH; ld = H_; tt = t - NTB_X; }
        const int k0 = tt * 64;
        const uint32_t base = smb + s * STG_B;
#pragma unroll
        for (int i = 0; i < 2; i++) {
            int lin = tid + i * 512, r = lin >> 3, c = lin & 7;
            cpa16(base + r * 144 + c * 16,       Ab + (size_t)(m0 + r) * ld + k0 + c * 8);
            cpa16(base + BST + r * 144 + c * 16, Wb + (size_t)(n0 + r) * ld + k0 + c * 8);
        }
        cp_commit();
    };

    issue(0, 0); issue(1, 1);
    for (int t = 0; t < NTB; t++) {
        if (t + 1 < NTB) cp_wait<1>(); else cp_wait<0>();
        __syncthreads();
        if (t + 2 < NTB) issue(t + 2, (t + 2) % 3);
        const uint32_t base = smb + (t % 3) * STG_B;
        const bool px = (t < NTB_X);
#pragma unroll
        for (int ks = 0; ks < 4; ks++) {
            const int kb = ks * 32;   // bytes
            uint32_t af[2][4];
#pragma unroll
            for (int mt = 0; mt < 2; mt++)
                ldsm4(af[mt][0], af[mt][1], af[mt][2], af[mt][3],
                      base + (wm * 32 + mt * 16 + l16) * 144 + kb + kh * 16);
#pragma unroll
            for (int nt = 0; nt < 2; nt++) {
                uint32_t r0, r1, r2, r3;
                ldsm4(r0, r1, r2, r3,
                      base + BST + (wn * 32 + nt * 16 + l16) * 144 + kb + kh * 16);
                uint32_t b0[2] = {r0, r2}, b1[2] = {r1, r3};
                if (px) {
#pragma unroll
                    for (int mt = 0; mt < 2; mt++) {
                        mma16816(ax[mt][nt * 2],     af[mt], b0);
                        mma16816(ax[mt][nt * 2 + 1], af[mt], b1);
                    }
                } else {
#pragma unroll
                    for (int mt = 0; mt < 2; mt++) {
                        mma16816(ah[mt][nt * 2],     af[mt], b0);
                        mma16816(ah[mt][nt * 2 + 1], af[mt], b1);
                    }
                }
            }
        }
    }

#pragma unroll
    for (int mt = 0; mt < 2; mt++)
#pragma unroll
        for (int q = 0; q < 4; q++) {
            const int nl = wn * 32 + q * 8 + ti * 2;
            const int n = n0 + nl;
#pragma unroll
            for (int h = 0; h < 2; h++) {
                const int m = m0 + wm * 32 + mt * 16 + g + h * 8;
                float v0 = (ax[mt][q][h * 2 + 0] + bs[nl + 0]) *
                           (ah[mt][q][h * 2 + 0] + bs[128 + nl + 0]);
                float v1 = (ax[mt][q][h * 2 + 1] + bs[nl + 1]) *
                           (ah[mt][q][h * 2 + 1] + bs[128 + nl + 1]);
                __nv_bfloat162 p = __float22bfloat162_rn(make_float2(v0, v1));
                *(unsigned*)(g_mtb + (size_t)m * H_ + n) = *(unsigned*)&p;
                *(uint16_t*)(g_mt8 + (size_t)m * H_ + n) =
                    fp8pair(v0 * 256.f, v1 * 256.f);
            }
        }
}

// c-gate: ct = tanh(x@Wcx + m_t@Wcm + b) -> fp32
__global__ __launch_bounds__(512, 1)
void gemm_c(const float* __restrict__ bcx, const float* __restrict__ bcm) {
    extern __shared__ __align__(16) char sm[];
    const uint32_t smb = smem_u32(sm);
    float* bs = (float*)(sm + 3 * STG_B);

    const int m0 = blockIdx.y * 128;
    const int n0 = blockIdx.x * 128;
    const int tid = threadIdx.x, lane = tid & 31, warp = tid >> 5;
    const int wm = warp & 3, wn = warp >> 2;
    const int g = lane >> 2, ti = lane & 3;
    const int l16 = lane & 15, kh = lane >> 4;

    if (tid < 128) bs[tid] = bcx[n0 + tid] + bcm[n0 + tid];

    float acc[2][4][4];
#pragma unroll
    for (int mt = 0; mt < 2; mt++)
#pragma unroll
        for (int q = 0; q < 4; q++)
#pragma unroll
            for (int j = 0; j < 4; j++) acc[mt][q][j] = 0.f;

    auto issue = [&](int t, int s) {
        const __nv_bfloat16 *Ab, *Wb; int ld; int tt = t;
        if (t < NTB_X) { Ab = g_xb;  Wb = g_wbf + OFF_CX; ld = E_; }
        else           { Ab = g_mtb; Wb = g_wbf + OFF_CM; ld = H_; tt = t - NTB_X; }
        const int k0 = tt * 64;
        const uint32_t base = smb + s * STG_B;
#pragma unroll
        for (int i = 0; i < 2; i++) {
            int lin = tid + i * 512, r = lin >> 3, c = lin & 7;
            cpa16(base + r * 144 + c * 16,       Ab + (size_t)(m0 + r) * ld + k0 + c * 8);
            cpa16(base + BST + r * 144 + c * 16, Wb + (size_t)(n0 + r) * ld + k0 + c * 8);
        }
        cp_commit();
    };

    issue(0, 0); issue(1, 1);
    for (int t = 0; t < NTB; t++) {
        if (t + 1 < NTB) cp_wait<1>(); else cp_wait<0>();
        __syncthreads();
        if (t + 2 < NTB) issue(t + 2, (t + 2) % 3);
        const uint32_t base = smb + (t % 3) * STG_B;
#pragma unroll
        for (int ks = 0; ks < 4; ks++) {
            const int kb = ks * 32;
            uint32_t af[2][4];
#pragma unroll
            for (int mt = 0; mt < 2; mt++)
                ldsm4(af[mt][0], af[mt][1], af[mt][2], af[mt][3],
                      base + (wm * 32 + mt * 16 + l16) * 144 + kb + kh * 16);
#pragma unroll
            for (int nt = 0; nt < 2; nt++) {
                uint32_t r0, r1, r2, r3;
                ldsm4(r0, r1, r2, r3,
                      base + BST + (wn * 32 + nt * 16 + l16) * 144 + kb + kh * 16);
                uint32_t b0[2] = {r0, r2}, b1[2] = {r1, r3};
#pragma unroll
                for (int mt = 0; mt < 2; mt++) {
                    mma16816(acc[mt][nt * 2],     af[mt], b0);
                    mma16816(acc[mt][nt * 2 + 1], af[mt], b1);
                }
            }
        }
    }

#pragma unroll
    for (int mt = 0; mt < 2; mt++)
#pragma unroll
        for (int q = 0; q < 4; q++) {
            const int nl = wn * 32 + q * 8 + ti * 2;
            const int n = n0 + nl;
#pragma unroll
            for (int h = 0; h < 2; h++) {
                const int m = m0 + wm * 32 + mt * 16 + g + h * 8;
                float2 v;
                v.x = tanhf_(acc[mt][q][h * 2 + 0] + bs[nl + 0]);
                v.y = tanhf_(acc[mt][q][h * 2 + 1] + bs[nl + 1]);
                *(float2*)(g_ct + (size_t)m * H_ + n) = v;
            }
        }
}

// ---------------------------------------------------------------------------
// f,i,o (fp8 QMMA): BM=128, BN=64, BK=128 B, 512 thr, 3 gates fused,
// 3-stage pipeline, one sync per k-tile; rows 144 B.
// ---------------------------------------------------------------------------
#define LDSF   144
#define GK_AS  18432
#define GK_BS  9216
#define GK_STG (GK_AS + 3 * GK_BS)
#define GK_SMEM (3 * GK_STG + 1024)
#define GK_NT  24
#define GK_NX  8

__global__ __launch_bounds__(512, 1)
void gemm_fio(const float* __restrict__ bfx, const float* __restrict__ bfm,
              const float* __restrict__ bix, const float* __restrict__ bim,
              const float* __restrict__ box_, const float* __restrict__ bom,
              const float* __restrict__ c0,
              float* __restrict__ hx, float* __restrict__ cx) {
    extern __shared__ __align__(16) char sm[];
    const uint32_t smb = smem_u32(sm);
    float* bs = (float*)(sm + 3 * GK_STG);

    const int m0 = blockIdx.y * 128;
    const int n0 = blockIdx.x * 64;
    const int tid = threadIdx.x, lane = tid & 31, warp = tid >> 5;
    const int wm = warp & 3, wn = warp >> 2;
    const int g = lane >> 2, ti = lane & 3;
    const int l16 = lane & 15, kh = lane >> 4;

    if (tid < 64) {
        const int n = n0 + tid;
        bs[0 * 64 + tid] = bfx[n] + bfm[n];
        bs[1 * 64 + tid] = bix[n] + bim[n];
        bs[2 * 64 + tid] = box_[n] + bom[n];
    }

    float acc[3][2][2][4];
#pragma unroll
    for (int z = 0; z < 3; z++)
#pragma unroll
        for (int mt = 0; mt < 2; mt++)
#pragma unroll
            for (int nt = 0; nt < 2; nt++)
#pragma unroll
                for (int j = 0; j < 4; j++) acc[z][mt][nt][j] = 0.f;

    auto issue = [&](int t, int s) {
        const bool xph = (t < GK_NX);
        const uint8_t* Ab = xph ? g_x8 : g_mt8;
        const int ld = xph ? E_ : H_;
        const int k0 = (xph ? t : t - GK_NX) * 128;
        const uint32_t base = smb + s * GK_STG;
#pragma unroll
        for (int i = 0; i < 2; i++) {
            int lin = tid + i * 512, r = lin >> 3, c = lin & 7;
            cpa16(base + r * LDSF + c * 16,
                  Ab + (size_t)(m0 + r) * ld + k0 + c * 16);
        }
#pragma unroll
        for (int i = 0; i < 3; i++) {
            int lin = tid + i * 512;
            int z = lin >> 9, rr = (lin >> 3) & 63, cc = lin & 7;
            const uint8_t* Wb = g_w8 + (xph ? OFF8_ZX(z) : OFF8_ZM(z));
            cpa16(base + GK_AS + z * GK_BS + rr * LDSF + cc * 16,
                  Wb + (size_t)(n0 + rr) * ld + k0 + cc * 16);
        }
        cp_commit();
    };

    issue(0, 0); issue(1, 1);
    for (int t = 0; t < GK_NT; t++) {
        if (t + 1 < GK_NT) cp_wait<1>(); else cp_wait<0>();
        __syncthreads();
        if (t + 2 < GK_NT) issue(t + 2, (t + 2) % 3);

        if (t == GK_NX) {
#pragma unroll
            for (int z = 0; z < 3; z++)
#pragma unroll
                for (int mt = 0; mt < 2; mt++)
#pragma unroll
                    for (int nt = 0; nt < 2; nt++)
#pragma unroll
                        for (int j = 0; j < 4; j++) acc[z][mt][nt][j] *= 4.f;
        }

        const uint32_t base = smb + (t % 3) * GK_STG;
#pragma unroll
        for (int ks = 0; ks < 4; ks++) {
            const int kb = ks * 32;
            uint32_t af[2][4];
#pragma unroll
            for (int mt = 0; mt < 2; mt++)
                ldsm4(af[mt][0], af[mt][1], af[mt][2], af[mt][3],
                      base + (wm * 32 + mt * 16 + l16) * LDSF + kb + kh * 16);
#pragma unroll
            for (int z = 0; z < 3; z++) {
                uint32_t r0, r1, r2, r3;
                ldsm4(r0, r1, r2, r3,
                      base + GK_AS + z * GK_BS + (wn * 16 + l16) * LDSF + kb + kh * 16);
                uint32_t b0[2] = {r0, r2}, b1[2] = {r1, r3};
#pragma unroll
                for (int mt = 0; mt < 2; mt++) {
                    mma_fp8(acc[z][mt][0], af[mt], b0);
                    mma_fp8(acc[z][mt][1], af[mt], b1);
                }
            }
        }
    }

    constexpr float DQ = 1.f / 16384.f;
#pragma unroll
    for (int mt = 0; mt < 2; mt++)
#pragma unroll
        for (int nt = 0; nt < 2; nt++) {
            const int nl = wn * 16 + nt * 8 + ti * 2;
            const int n = n0 + nl;
#pragma unroll
            for (int h = 0; h < 2; h++) {
                const int m = m0 + wm * 32 + mt * 16 + g + h * 8;
                float2 c0v = *(const float2*)(c0 + (size_t)m * H_ + n);
                float2 ctv = *(const float2*)(g_ct + (size_t)m * H_ + n);
                float2 hv, cvv;
#pragma unroll
                for (int j = 0; j < 2; j++) {
                    const int e = h * 2 + j;
                    float fg = sigf(acc[0][mt][nt][e] * DQ + bs[0 * 64 + nl + j]);
                    float ig = sigf(acc[1][mt][nt][e] * DQ + bs[1 * 64 + nl + j]);
                    float og = sigf(acc[2][mt][nt][e] * DQ + bs[2 * 64 + nl + j]);
                    float ct  = j ? ctv.y : ctv.x;
                    float c0e = j ? c0v.y : c0v.x;
                    float cv = fg * c0e + ig * ct;
                    ((float*)&cvv)[j] = cv;
                    ((float*)&hv)[j]  = og * tanhf_(cv);
                }
                *(float2*)(cx + (size_t)m * H_ + n) = cvv;
                *(float2*)(hx + (size_t)m * H_ + n) = hv;
            }
        }
}

// ---------------------------------------------------------------------------
// decoder
// ---------------------------------------------------------------------------
__global__ void decoder(const float* __restrict__ hx, const float* __restrict__ Wd,
                        const float* __restrict__ bd, float* __restrict__ out) {
    const int gw = (blockIdx.x * blockDim.x + threadIdx.x) >> 5;
    const int lane = threadIdx.x & 31;
    if (gw >= B_) return;
    const float4* h4 = (const float4*)(hx + (size_t)gw * H_);
    const float4* w0 = (const float4*)(Wd);
    const float4* w1 = (const float4*)(Wd + H_);
    float s0 = 0.f, s1 = 0.f;
    for (int i = lane; i < H_ / 4; i += 32) {
        float4 h = h4[i], a = w0[i], b = w1[i];
        s0 += h.x * a.x + h.y * a.y + h.z * a.z + h.w * a.w;
        s1 += h.x * b.x + h.y * b.y + h.z * b.z + h.w * b.w;
    }
#pragma unroll
    for (int o = 16; o; o >>= 1) {
        s0 += __shfl_xor_sync(0xFFFFFFFFu, s0, o);
        s1 += __shfl_xor_sync(0xFFFFFFFFu, s1, o);
    }
    if (lane == 0) {
        out[(size_t)gw * 2 + 0] = s0 + bd[0];
        out[(size_t)gw * 2 + 1] = s1 + bd[1];
    }
}

// ---------------------------------------------------------------------------
extern "C" void kernel_launch(void* const* d_in, const int* in_sizes, int n_in,
                              void* d_out, int out_size) {
    const int*   inp  = (const int*)  d_in[0];
    const float* h0   = (const float*)d_in[1];
    const float* c0   = (const float*)d_in[2];
    const float* emb  = (const float*)d_in[3];
    const float *W_mx = (const float*)d_in[4],  *b_mx = (const float*)d_in[5];
    const float *W_mh = (const float*)d_in[6],  *b_mh = (const float*)d_in[7];
    const float *W_fx = (const float*)d_in[8],  *b_fx = (const float*)d_in[9];
    const float *W_fm = (const float*)d_in[10], *b_fm = (const float*)d_in[11];
    const float *W_ix = (const float*)d_in[12], *b_ix = (const float*)d_in[13];
    const float *W_im = (const float*)d_in[14], *b_im = (const float*)d_in[15];
    const float *W_ox = (const float*)d_in[16], *b_ox = (const float*)d_in[17];
    const float *W_om = (const float*)d_in[18], *b_om = (const float*)d_in[19];
    const float *W_cx = (const float*)d_in[20], *b_cx = (const float*)d_in[21];
    const float *W_cm = (const float*)d_in[22], *b_cm = (const float*)d_in[23];
    const float *W_dec= (const float*)d_in[24], *b_dec= (const float*)d_in[25];
    float* out = (float*)d_out;

    __nv_bfloat16 *wbf, *h0b;
    uint8_t *w8;
    cudaGetSymbolAddress((void**)&wbf, g_wbf);
    cudaGetSymbolAddress((void**)&h0b, g_h0b);
    cudaGetSymbolAddress((void**)&w8,  g_w8);

    // 1) bf16 conversions
    Cvt5 c5;
    c5.s[0] = W_mx; c5.d[0] = wbf + OFF_MX; c5.n4[0] = 2 * MEG / 4;
    c5.s[1] = W_mh; c5.d[1] = wbf + OFF_MH; c5.n4[1] = 4 * MEG / 4;
    c5.s[2] = W_cx; c5.d[2] = wbf + OFF_CX; c5.n4[2] = 2 * MEG / 4;
    c5.s[3] = W_cm; c5.d[3] = wbf + OFF_CM; c5.n4[3] = 4 * MEG / 4;
    c5.s[4] = h0;   c5.d[4] = h0b;          c5.n4[4] = 16 * MEG / 4;
    cvt_f32_bf16<<<dim3(1024, 5), 256>>>(c5);

    // 2) fp8 conversions
    Cvt6 c6;
    const float* gs[6] = {W_fx, W_fm, W_ix, W_im, W_ox, W_om};
    for (int z = 0; z < 3; z++) {
        c6.s[2*z]   = gs[2*z];   c6.d[2*z]   = w8 + OFF8_ZX(z); c6.n4[2*z]   = 2 * MEG / 4;
        c6.s[2*z+1] = gs[2*z+1]; c6.d[2*z+1] = w8 + OFF8_ZM(z); c6.n4[2*z+1] = 4 * MEG / 4;
    }
    cvt_f32_fp8<<<dim3(1024, 6), 256>>>(c6);

    // 3) gather
    gather_x<<<B_, 256>>>(inp, emb);

    // 4) m_t
    cudaFuncSetAttribute(gemm_mt, cudaFuncAttributeMaxDynamicSharedMemorySize, BF_SMEM);
    gemm_mt<<<dim3(H_ / 128, B_ / 128), 512, BF_SMEM>>>(b_mx, b_mh);

    // 5) ct
    cudaFuncSetAttribute(gemm_c, cudaFuncAttributeMaxDynamicSharedMemorySize, BF_SMEM);
    gemm_c<<<dim3(H_ / 128, B_ / 128), 512, BF_SMEM>>>(b_cx, b_cm);

    // 6) f,i,o + cx/hx
    float* hx_out = out + 2 * (size_t)B_;
    float* cx_out = hx_out + (size_t)B_ * H_;
    cudaFuncSetAttribute(gemm_fio, cudaFuncAttributeMaxDynamicSharedMemorySize, GK_SMEM);
    gemm_fio<<<dim3(H_ / 64, B_ / 128), 512, GK_SMEM>>>(
        b_fx, b_fm, b_ix, b_im, b_ox, b_om, c0, hx_out, cx_out);

    // 7) decoder
    decoder<<<(B_ * 32) / 256, 256>>>(hx_out, W_dec, b_dec, out);
}

// round 10
// speedup vs baseline: 1.3834x; 1.0225x over previous
#include <cuda_runtime.h>
#include <cuda_bf16.h>
#include <cuda_fp8.h>
#include <cstdint>

// ---------------------------------------------------------------------------
// mLSTM single step, B=8192, V=50257, E=1024, H=2048, O=2
//   x   = emb[inp]
//   m_t = (x@W_mx^T + b_mx) * (h0@W_mh^T + b_mh)            [bf16 HMMA]
//   ct  = tanh(x@W_cx^T + m_t@W_cm^T + b)                   [bf16 HMMA]
//   z_o = x@W_ox^T + m_t@W_om^T + b                         [fp8 QMMA] -> bf16
//   f,i = sigmoid(x@W_zx^T + m_t@W_zm^T + b)                [fp8 QMMA]
//   cx  = f*c0 + i*ct ; hx = sigmoid(z_o)*tanh(cx) ; out = hx@W_dec^T + b_dec
// d_out: [ out(B,2) | hx(B,H) | cx(B,H) ]  fp32
//
// All GEMMs: BM=128, BN=128, 512 thr (16 warps 4x4, warp tile 32x32),
// 3-stage cp.async pipeline, one __syncthreads per k-tile, 144B row stride.
// bf16: BK=64. fp8: BK=128 with scales x*64, W*64, m_t*256; x-phase acc*4 at
// boundary; dequant 2^-14.
// ---------------------------------------------------------------------------

#define B_  8192
#define E_  1024
#define H_  2048
#define MEG (1 << 20)

__device__ __align__(16) __nv_bfloat16 g_xb [(size_t)B_ * E_];   // 16 MB bf16 x
__device__ __align__(16) __nv_bfloat16 g_h0b[(size_t)B_ * H_];   // 32 MB bf16 h0
__device__ __align__(16) __nv_bfloat16 g_mtb[(size_t)B_ * H_];   // 32 MB bf16 m_t
__device__ __align__(16) __nv_bfloat16 g_zo [(size_t)B_ * H_];   // 32 MB bf16 z_o pre-act
__device__ __align__(16) __nv_bfloat16 g_wbf[(size_t)12 * MEG];  // 24 MB bf16 W_mx,W_mh,W_cx,W_cm
__device__ __align__(16) float         g_ct [(size_t)B_ * H_];   // 64 MB fp32 c~
__device__ __align__(16) uint8_t       g_x8 [(size_t)B_ * E_];   //  8 MB fp8 x*64
__device__ __align__(16) uint8_t       g_mt8[(size_t)B_ * H_];   // 16 MB fp8 m_t*256
__device__ __align__(16) uint8_t       g_w8 [(size_t)18 * MEG];  // 18 MB fp8 f,i,o W*64

#define OFF_MX 0
#define OFF_MH (2 * MEG)
#define OFF_CX (6 * MEG)
#define OFF_CM (8 * MEG)
#define OFF8_ZX(z) ((size_t)(z) * 6 * MEG)            // z: 0=f 1=i 2=o
#define OFF8_ZM(z) ((size_t)(z) * 6 * MEG + 2 * MEG)

// ---------------------------------------------------------------------------
// helpers
// ---------------------------------------------------------------------------
__device__ __forceinline__ uint32_t smem_u32(const void* p) {
    uint32_t a;
    asm("{ .reg .u64 t; cvta.to.shared.u64 t, %1; cvt.u32.u64 %0, t; }"
        : "=r"(a) : "l"(p));
    return a;
}
__device__ __forceinline__ void cpa16(uint32_t dst, const void* src) {
    asm volatile("cp.async.cg.shared.global [%0], [%1], 16;\n" :: "r"(dst), "l"(src));
}
__device__ __forceinline__ void cp_commit() { asm volatile("cp.async.commit_group;\n" ::); }
template <int N> __device__ __forceinline__ void cp_wait() {
    asm volatile("cp.async.wait_group %0;\n" :: "n"(N));
}
__device__ __forceinline__ void ldsm4(uint32_t& r0, uint32_t& r1, uint32_t& r2,
                                      uint32_t& r3, uint32_t addr) {
    asm volatile("ldmatrix.sync.aligned.m8n8.x4.shared.b16 {%0,%1,%2,%3}, [%4];"
                 : "=r"(r0), "=r"(r1), "=r"(r2), "=r"(r3) : "r"(addr));
}
__device__ __forceinline__ void mma16816(float c[4], const uint32_t a[4], const uint32_t b[2]) {
    asm volatile(
        "mma.sync.aligned.m16n8k16.row.col.f32.bf16.bf16.f32 "
        "{%0,%1,%2,%3}, {%4,%5,%6,%7}, {%8,%9}, {%0,%1,%2,%3};\n"
        : "+f"(c[0]), "+f"(c[1]), "+f"(c[2]), "+f"(c[3])
        : "r"(a[0]), "r"(a[1]), "r"(a[2]), "r"(a[3]), "r"(b[0]), "r"(b[1]));
}
__device__ __forceinline__ void mma_fp8(float c[4], const uint32_t a[4], const uint32_t b[2]) {
    asm volatile(
        "mma.sync.aligned.m16n8k32.row.col.f32.e4m3.e4m3.f32 "
        "{%0,%1,%2,%3}, {%4,%5,%6,%7}, {%8,%9}, {%0,%1,%2,%3};\n"
        : "+f"(c[0]), "+f"(c[1]), "+f"(c[2]), "+f"(c[3])
        : "r"(a[0]), "r"(a[1]), "r"(a[2]), "r"(a[3]), "r"(b[0]), "r"(b[1]));
}
__device__ __forceinline__ uint16_t fp8pair(float v0, float v1) {
    uint16_t r;
    asm("cvt.rn.satfinite.e4m3x2.f32 %0, %1, %2;" : "=h"(r) : "f"(v1), "f"(v0));
    return r;
}
__device__ __forceinline__ float sigf(float v)   { return 1.f / (1.f + __expf(-v)); }
__device__ __forceinline__ float tanhf_(float v) { return fmaf(2.f, 1.f / (1.f + __expf(-2.f * v)), -1.f); }

// ---------------------------------------------------------------------------
// conversions + gather
// ---------------------------------------------------------------------------
struct Cvt5 { const float* s[5]; __nv_bfloat16* d[5]; int n4[5]; };

__global__ void cvt_f32_bf16(Cvt5 a) {
    const int seg = blockIdx.y;
    const float4* __restrict__ s = (const float4*)a.s[seg];
    uint2* __restrict__ d = (uint2*)a.d[seg];
    const int n4 = a.n4[seg];
    for (int i = blockIdx.x * blockDim.x + threadIdx.x; i < n4;
         i += gridDim.x * blockDim.x) {
        float4 v = s[i];
        __nv_bfloat162 lo = __float22bfloat162_rn(make_float2(v.x, v.y));
        __nv_bfloat162 hi = __float22bfloat162_rn(make_float2(v.z, v.w));
        uint2 o; o.x = *(unsigned*)&lo; o.y = *(unsigned*)&hi;
        d[i] = o;
    }
}

struct Cvt6 { const float* s[6]; uint8_t* d[6]; int n4[6]; };

__global__ void cvt_f32_fp8(Cvt6 a) {
    const int seg = blockIdx.y;
    const float4* __restrict__ s = (const float4*)a.s[seg];
    uint32_t* __restrict__ d = (uint32_t*)a.d[seg];
    const int n4 = a.n4[seg];
    for (int i = blockIdx.x * blockDim.x + threadIdx.x; i < n4;
         i += gridDim.x * blockDim.x) {
        float4 v = s[i];
        uint32_t lo = fp8pair(v.x * 64.f, v.y * 64.f);
        uint32_t hi = fp8pair(v.z * 64.f, v.w * 64.f);
        d[i] = lo | (hi << 16);
    }
}

__global__ void gather_x(const int* __restrict__ inp, const float* __restrict__ emb) {
    const int b = blockIdx.x;
    const int v = inp[b];
    float4 t = ((const float4*)(emb + (size_t)v * E_))[threadIdx.x];
    __nv_bfloat162 lo = __float22bfloat162_rn(make_float2(t.x, t.y));
    __nv_bfloat162 hi = __float22bfloat162_rn(make_float2(t.z, t.w));
    uint2 o; o.x = *(unsigned*)&lo; o.y = *(unsigned*)&hi;
    ((uint2*)(g_xb + (size_t)b * E_))[threadIdx.x] = o;
    uint32_t l8 = fp8pair(t.x * 64.f, t.y * 64.f);
    uint32_t h8 = fp8pair(t.z * 64.f, t.w * 64.f);
    ((uint32_t*)(g_x8 + (size_t)b * E_))[threadIdx.x] = l8 | (h8 << 16);
}

// ---------------------------------------------------------------------------
// bf16 GEMMs: BM=128, BN=128, BK=64; rows 144 B; 3 stages; one sync/iter
// ---------------------------------------------------------------------------
#define BST    18432                 // 128 rows * 144 B
#define STG_B  (2 * BST)
#define BF_SMEM (3 * STG_B + 1024)
#define NTB_X  16
#define NTB    48

// m_t: dual accumulation -> bf16 + fp8*256
__global__ __launch_bounds__(512, 1)
void gemm_mt(const float* __restrict__ b_mx, const float* __restrict__ b_mh) {
    extern __shared__ __align__(16) char sm[];
    const uint32_t smb = smem_u32(sm);
    float* bs = (float*)(sm + 3 * STG_B);

    const int m0 = blockIdx.y * 128;
    const int n0 = blockIdx.x * 128;
    const int tid = threadIdx.x, lane = tid & 31, warp = tid >> 5;
    const int wm = warp & 3, wn = warp >> 2;
    const int g = lane >> 2, ti = lane & 3;
    const int l16 = lane & 15, kh = lane >> 4;

    if (tid < 128) {
        bs[tid]       = b_mx[n0 + tid];
        bs[128 + tid] = b_mh[n0 + tid];
    }

    float ax[2][4][4], ah[2][4][4];
#pragma unroll
    for (int mt = 0; mt < 2; mt++)
#pragma unroll
        for (int q = 0; q < 4; q++)
#pragma unroll
            for (int j = 0; j < 4; j++) { ax[mt][q][j] = 0.f; ah[mt][q][j] = 0.f; }

    auto issue = [&](int t, int s) {
        const __nv_bfloat16 *Ab, *Wb; int ld; int tt = t;
        if (t < NTB_X) { Ab = g_xb;  Wb = g_wbf + OFF_MX; ld = E_; }
        else           { Ab = g_h0b; Wb = g_wbf + OFF_MH; ld = H_; tt = t - NTB_X; }
        const int k0 = tt * 64;
        const uint32_t base = smb + s * STG_B;
#pragma unroll
        for (int i = 0; i < 2; i++) {
            int lin = tid + i * 512, r = lin >> 3, c = lin & 7;
            cpa16(base + r * 144 + c * 16,       Ab + (size_t)(m0 + r) * ld + k0 + c * 8);
            cpa16(base + BST + r * 144 + c * 16, Wb + (size_t)(n0 + r) * ld + k0 + c * 8);
        }
        cp_commit();
    };

    issue(0, 0); issue(1, 1);
    for (int t = 0; t < NTB; t++) {
        if (t + 1 < NTB) cp_wait<1>(); else cp_wait<0>();
        __syncthreads();
        if (t + 2 < NTB) issue(t + 2, (t + 2) % 3);
        const uint32_t base = smb + (t % 3) * STG_B;
        const bool px = (t < NTB_X);
#pragma unroll
        for (int ks = 0; ks < 4; ks++) {
            const int kb = ks * 32;
            uint32_t af[2][4];
#pragma unroll
            for (int mt = 0; mt < 2; mt++)
                ldsm4(af[mt][0], af[mt][1], af[mt][2], af[mt][3],
                      base + (wm * 32 + mt * 16 + l16) * 144 + kb + kh * 16);
#pragma unroll
            for (int nt = 0; nt < 2; nt++) {
                uint32_t r0, r1, r2, r3;
                ldsm4(r0, r1, r2, r3,
                      base + BST + (wn * 32 + nt * 16 + l16) * 144 + kb + kh * 16);
                uint32_t b0[2] = {r0, r2}, b1[2] = {r1, r3};
                if (px) {
#pragma unroll
                    for (int mt = 0; mt < 2; mt++) {
                        mma16816(ax[mt][nt * 2],     af[mt], b0);
                        mma16816(ax[mt][nt * 2 + 1], af[mt], b1);
                    }
                } else {
#pragma unroll
                    for (int mt = 0; mt < 2; mt++) {
                        mma16816(ah[mt][nt * 2],     af[mt], b0);
                        mma16816(ah[mt][nt * 2 + 1], af[mt], b1);
                    }
                }
            }
        }
    }

#pragma unroll
    for (int mt = 0; mt < 2; mt++)
#pragma unroll
        for (int q = 0; q < 4; q++) {
            const int nl = wn * 32 + q * 8 + ti * 2;
            const int n = n0 + nl;
#pragma unroll
            for (int h = 0; h < 2; h++) {
                const int m = m0 + wm * 32 + mt * 16 + g + h * 8;
                float v0 = (ax[mt][q][h * 2 + 0] + bs[nl + 0]) *
                           (ah[mt][q][h * 2 + 0] + bs[128 + nl + 0]);
                float v1 = (ax[mt][q][h * 2 + 1] + bs[nl + 1]) *
                           (ah[mt][q][h * 2 + 1] + bs[128 + nl + 1]);
                __nv_bfloat162 p = __float22bfloat162_rn(make_float2(v0, v1));
                *(unsigned*)(g_mtb + (size_t)m * H_ + n) = *(unsigned*)&p;
                *(uint16_t*)(g_mt8 + (size_t)m * H_ + n) =
                    fp8pair(v0 * 256.f, v1 * 256.f);
            }
        }
}

// c-gate: ct = tanh(x@Wcx + m_t@Wcm + b) -> fp32
__global__ __launch_bounds__(512, 1)
void gemm_c(const float* __restrict__ bcx, const float* __restrict__ bcm) {
    extern __shared__ __align__(16) char sm[];
    const uint32_t smb = smem_u32(sm);
    float* bs = (float*)(sm + 3 * STG_B);

    const int m0 = blockIdx.y * 128;
    const int n0 = blockIdx.x * 128;
    const int tid = threadIdx.x, lane = tid & 31, warp = tid >> 5;
    const int wm = warp & 3, wn = warp >> 2;
    const int g = lane >> 2, ti = lane & 3;
    const int l16 = lane & 15, kh = lane >> 4;

    if (tid < 128) bs[tid] = bcx[n0 + tid] + bcm[n0 + tid];

    float acc[2][4][4];
#pragma unroll
    for (int mt = 0; mt < 2; mt++)
#pragma unroll
        for (int q = 0; q < 4; q++)
#pragma unroll
            for (int j = 0; j < 4; j++) acc[mt][q][j] = 0.f;

    auto issue = [&](int t, int s) {
        const __nv_bfloat16 *Ab, *Wb; int ld; int tt = t;
        if (t < NTB_X) { Ab = g_xb;  Wb = g_wbf + OFF_CX; ld = E_; }
        else           { Ab = g_mtb; Wb = g_wbf + OFF_CM; ld = H_; tt = t - NTB_X; }
        const int k0 = tt * 64;
        const uint32_t base = smb + s * STG_B;
#pragma unroll
        for (int i = 0; i < 2; i++) {
            int lin = tid + i * 512, r = lin >> 3, c = lin & 7;
            cpa16(base + r * 144 + c * 16,       Ab + (size_t)(m0 + r) * ld + k0 + c * 8);
            cpa16(base + BST + r * 144 + c * 16, Wb + (size_t)(n0 + r) * ld + k0 + c * 8);
        }
        cp_commit();
    };

    issue(0, 0); issue(1, 1);
    for (int t = 0; t < NTB; t++) {
        if (t + 1 < NTB) cp_wait<1>(); else cp_wait<0>();
        __syncthreads();
        if (t + 2 < NTB) issue(t + 2, (t + 2) % 3);
        const uint32_t base = smb + (t % 3) * STG_B;
#pragma unroll
        for (int ks = 0; ks < 4; ks++) {
            const int kb = ks * 32;
            uint32_t af[2][4];
#pragma unroll
            for (int mt = 0; mt < 2; mt++)
                ldsm4(af[mt][0], af[mt][1], af[mt][2], af[mt][3],
                      base + (wm * 32 + mt * 16 + l16) * 144 + kb + kh * 16);
#pragma unroll
            for (int nt = 0; nt < 2; nt++) {
                uint32_t r0, r1, r2, r3;
                ldsm4(r0, r1, r2, r3,
                      base + BST + (wn * 32 + nt * 16 + l16) * 144 + kb + kh * 16);
                uint32_t b0[2] = {r0, r2}, b1[2] = {r1, r3};
#pragma unroll
                for (int mt = 0; mt < 2; mt++) {
                    mma16816(acc[mt][nt * 2],     af[mt], b0);
                    mma16816(acc[mt][nt * 2 + 1], af[mt], b1);
                }
            }
        }
    }

#pragma unroll
    for (int mt = 0; mt < 2; mt++)
#pragma unroll
        for (int q = 0; q < 4; q++) {
            const int nl = wn * 32 + q * 8 + ti * 2;
            const int n = n0 + nl;
#pragma unroll
            for (int h = 0; h < 2; h++) {
                const int m = m0 + wm * 32 + mt * 16 + g + h * 8;
                float2 v;
                v.x = tanhf_(acc[mt][q][h * 2 + 0] + bs[nl + 0]);
                v.y = tanhf_(acc[mt][q][h * 2 + 1] + bs[nl + 1]);
                *(float2*)(g_ct + (size_t)m * H_ + n) = v;
            }
        }
}

// ---------------------------------------------------------------------------
// fp8 GEMMs: BM=128, BN=128, BK=128 B; rows 144 B; 3 stages; one sync/iter
// x-phase 8 iters (K=1024), m-phase 16 iters (K=2048); acc*4 at boundary.
// ---------------------------------------------------------------------------
#define F8_NT  24
#define F8_NX  8
#define DQ_    (1.f / 16384.f)

// o-gate: z_o = x@Wox + m_t@Wom + b  -> bf16 pre-act
#define O_STG  (2 * BST)
#define O_SMEM (3 * O_STG + 1024)

__global__ __launch_bounds__(512, 1)
void gemm_o(const float* __restrict__ box_, const float* __restrict__ bom) {
    extern __shared__ __align__(16) char sm[];
    const uint32_t smb = smem_u32(sm);
    float* bs = (float*)(sm + 3 * O_STG);

    const int m0 = blockIdx.y * 128;
    const int n0 = blockIdx.x * 128;
    const int tid = threadIdx.x, lane = tid & 31, warp = tid >> 5;
    const int wm = warp & 3, wn = warp >> 2;
    const int g = lane >> 2, ti = lane & 3;
    const int l16 = lane & 15, kh = lane >> 4;

    if (tid < 128) bs[tid] = box_[n0 + tid] + bom[n0 + tid];

    float acc[2][4][4];
#pragma unroll
    for (int mt = 0; mt < 2; mt++)
#pragma unroll
        for (int q = 0; q < 4; q++)
#pragma unroll
            for (int j = 0; j < 4; j++) acc[mt][q][j] = 0.f;

    auto issue = [&](int t, int s) {
        const bool xph = (t < F8_NX);
        const uint8_t* Ab = xph ? g_x8 : g_mt8;
        const uint8_t* Wb = g_w8 + (xph ? OFF8_ZX(2) : OFF8_ZM(2));
        const int ld = xph ? E_ : H_;
        const int k0 = (xph ? t : t - F8_NX) * 128;
        const uint32_t base = smb + s * O_STG;
#pragma unroll
        for (int i = 0; i < 2; i++) {
            int lin = tid + i * 512, r = lin >> 3, c = lin & 7;
            cpa16(base + r * 144 + c * 16,       Ab + (size_t)(m0 + r) * ld + k0 + c * 16);
            cpa16(base + BST + r * 144 + c * 16, Wb + (size_t)(n0 + r) * ld + k0 + c * 16);
        }
        cp_commit();
    };

    issue(0, 0); issue(1, 1);
    for (int t = 0; t < F8_NT; t++) {
        if (t + 1 < F8_NT) cp_wait<1>(); else cp_wait<0>();
        __syncthreads();
        if (t + 2 < F8_NT) issue(t + 2, (t + 2) % 3);
        if (t == F8_NX) {
#pragma unroll
            for (int mt = 0; mt < 2; mt++)
#pragma unroll
                for (int q = 0; q < 4; q++)
#pragma unroll
                    for (int j = 0; j < 4; j++) acc[mt][q][j] *= 4.f;
        }
        const uint32_t base = smb + (t % 3) * O_STG;
#pragma unroll
        for (int ks = 0; ks < 4; ks++) {
            const int kb = ks * 32;
            uint32_t af[2][4];
#pragma unroll
            for (int mt = 0; mt < 2; mt++)
                ldsm4(af[mt][0], af[mt][1], af[mt][2], af[mt][3],
                      base + (wm * 32 + mt * 16 + l16) * 144 + kb + kh * 16);
#pragma unroll
            for (int nt = 0; nt < 2; nt++) {
                uint32_t r0, r1, r2, r3;
                ldsm4(r0, r1, r2, r3,
                      base + BST + (wn * 32 + nt * 16 + l16) * 144 + kb + kh * 16);
                uint32_t b0[2] = {r0, r2}, b1[2] = {r1, r3};
#pragma unroll
                for (int mt = 0; mt < 2; mt++) {
                    mma_fp8(acc[mt][nt * 2],     af[mt], b0);
                    mma_fp8(acc[mt][nt * 2 + 1], af[mt], b1);
                }
            }
        }
    }

#pragma unroll
    for (int mt = 0; mt < 2; mt++)
#pragma unroll
        for (int q = 0; q < 4; q++) {
            const int nl = wn * 32 + q * 8 + ti * 2;
            const int n = n0 + nl;
#pragma unroll
            for (int h = 0; h < 2; h++) {
                const int m = m0 + wm * 32 + mt * 16 + g + h * 8;
                float v0 = acc[mt][q][h * 2 + 0] * DQ_ + bs[nl + 0];
                float v1 = acc[mt][q][h * 2 + 1] * DQ_ + bs[nl + 1];
                __nv_bfloat162 p = __float22bfloat162_rn(make_float2(v0, v1));
                *(unsigned*)(g_zo + (size_t)m * H_ + n) = *(unsigned*)&p;
            }
        }
}

// f,i gates + final combine: cx/hx into d_out
#define FI_STG (3 * BST)                 // A + 2 B tiles
#define FI_SMEM (3 * FI_STG + 1024)

__global__ __launch_bounds__(512, 1)
void gemm_fi(const float* __restrict__ bfx, const float* __restrict__ bfm,
             const float* __restrict__ bix, const float* __restrict__ bim,
             const float* __restrict__ c0,
             float* __restrict__ hx, float* __restrict__ cx) {
    extern __shared__ __align__(16) char sm[];
    const uint32_t smb = smem_u32(sm);
    float* bs = (float*)(sm + 3 * FI_STG);

    const int m0 = blockIdx.y * 128;
    const int n0 = blockIdx.x * 128;
    const int tid = threadIdx.x, lane = tid & 31, warp = tid >> 5;
    const int wm = warp & 3, wn = warp >> 2;
    const int g = lane >> 2, ti = lane & 3;
    const int l16 = lane & 15, kh = lane >> 4;

    if (tid < 128) {
        const int n = n0 + tid;
        bs[tid]       = bfx[n] + bfm[n];
        bs[128 + tid] = bix[n] + bim[n];
    }

    float acc[2][2][4][4];   // [z][mt][q][j]
#pragma unroll
    for (int z = 0; z < 2; z++)
#pragma unroll
        for (int mt = 0; mt < 2; mt++)
#pragma unroll
            for (int q = 0; q < 4; q++)
#pragma unroll
                for (int j = 0; j < 4; j++) acc[z][mt][q][j] = 0.f;

    auto issue = [&](int t, int s) {
        const bool xph = (t < F8_NX);
        const uint8_t* Ab = xph ? g_x8 : g_mt8;
        const int ld = xph ? E_ : H_;
        const int k0 = (xph ? t : t - F8_NX) * 128;
        const uint32_t base = smb + s * FI_STG;
#pragma unroll
        for (int i = 0; i < 2; i++) {   // A: 1024 chunks
            int lin = tid + i * 512, r = lin >> 3, c = lin & 7;
            cpa16(base + r * 144 + c * 16, Ab + (size_t)(m0 + r) * ld + k0 + c * 16);
        }
#pragma unroll
        for (int i = 0; i < 4; i++) {   // B: 2 gates x 1024 chunks
            int lin = tid + i * 512;
            int z = lin >> 10, rr = (lin >> 3) & 127, cc = lin & 7;
            const uint8_t* Wb = g_w8 + (xph ? OFF8_ZX(z) : OFF8_ZM(z));
            cpa16(base + BST + z * BST + rr * 144 + cc * 16,
                  Wb + (size_t)(n0 + rr) * ld + k0 + cc * 16);
        }
        cp_commit();
    };

    issue(0, 0); issue(1, 1);
    for (int t = 0; t < F8_NT; t++) {
        if (t + 1 < F8_NT) cp_wait<1>(); else cp_wait<0>();
        __syncthreads();
        if (t + 2 < F8_NT) issue(t + 2, (t + 2) % 3);
        if (t == F8_NX) {
#pragma unroll
            for (int z = 0; z < 2; z++)
#pragma unroll
                for (int mt = 0; mt < 2; mt++)
#pragma unroll
                    for (int q = 0; q < 4; q++)
#pragma unroll
                        for (int j = 0; j < 4; j++) acc[z][mt][q][j] *= 4.f;
        }
        const uint32_t base = smb + (t % 3) * FI_STG;
#pragma unroll
        for (int ks = 0; ks < 4; ks++) {
            const int kb = ks * 32;
            uint32_t af[2][4];
#pragma unroll
            for (int mt = 0; mt < 2; mt++)
                ldsm4(af[mt][0], af[mt][1], af[mt][2], af[mt][3],
                      base + (wm * 32 + mt * 16 + l16) * 144 + kb + kh * 16);
#pragma unroll
            for (int z = 0; z < 2; z++)
#pragma unroll
                for (int nt = 0; nt < 2; nt++) {
                    uint32_t r0, r1, r2, r3;
                    ldsm4(r0, r1, r2, r3,
                          base + BST + z * BST + (wn * 32 + nt * 16 + l16) * 144 + kb + kh * 16);
                    uint32_t b0[2] = {r0, r2}, b1[2] = {r1, r3};
#pragma unroll
                    for (int mt = 0; mt < 2; mt++) {
                        mma_fp8(acc[z][mt][nt * 2],     af[mt], b0);
                        mma_fp8(acc[z][mt][nt * 2 + 1], af[mt], b1);
                    }
                }
        }
    }

    // epilogue: f,i sigmoids + o (from z_o) + ct + c0 -> cx, hx
#pragma unroll
    for (int mt = 0; mt < 2; mt++)
#pragma unroll
        for (int q = 0; q < 4; q++) {
            const int nl = wn * 32 + q * 8 + ti * 2;
            const int n = n0 + nl;
#pragma unroll
            for (int h = 0; h < 2; h++) {
                const int m = m0 + wm * 32 + mt * 16 + g + h * 8;
                float2 c0v = *(const float2*)(c0 + (size_t)m * H_ + n);
                float2 ctv = *(const float2*)(g_ct + (size_t)m * H_ + n);
                unsigned zob = *(const unsigned*)(g_zo + (size_t)m * H_ + n);
                __nv_bfloat162 zo2 = *(__nv_bfloat162*)&zob;
                float2 hv, cvv;
#pragma unroll
                for (int j = 0; j < 2; j++) {
                    const int e = h * 2 + j;
                    float fg = sigf(acc[0][mt][q][e] * DQ_ + bs[nl + j]);
                    float ig = sigf(acc[1][mt][q][e] * DQ_ + bs[128 + nl + j]);
                    float og = sigf(j ? __bfloat162float(zo2.y)
                                      : __bfloat162float(zo2.x));
                    float ct  = j ? ctv.y : ctv.x;
                    float c0e = j ? c0v.y : c0v.x;
                    float cv = fg * c0e + ig * ct;
                    ((float*)&cvv)[j] = cv;
                    ((float*)&hv)[j]  = og * tanhf_(cv);
                }
                *(float2*)(cx + (size_t)m * H_ + n) = cvv;
                *(float2*)(hx + (size_t)m * H_ + n) = hv;
            }
        }
}

// ---------------------------------------------------------------------------
// decoder
// ---------------------------------------------------------------------------
__global__ void decoder(const float* __restrict__ hx, const float* __restrict__ Wd,
                        const float* __restrict__ bd, float* __restrict__ out) {
    const int gw = (blockIdx.x * blockDim.x + threadIdx.x) >> 5;
    const int lane = threadIdx.x & 31;
    if (gw >= B_) return;
    const float4* h4 = (const float4*)(hx + (size_t)gw * H_);
    const float4* w0 = (const float4*)(Wd);
    const float4* w1 = (const float4*)(Wd + H_);
    float s0 = 0.f, s1 = 0.f;
    for (int i = lane; i < H_ / 4; i += 32) {
        float4 h = h4[i], a = w0[i], b = w1[i];
        s0 += h.x * a.x + h.y * a.y + h.z * a.z + h.w * a.w;
        s1 += h.x * b.x + h.y * b.y + h.z * b.z + h.w * b.w;
    }
#pragma unroll
    for (int o = 16; o; o >>= 1) {
        s0 += __shfl_xor_sync(0xFFFFFFFFu, s0, o);
        s1 += __shfl_xor_sync(0xFFFFFFFFu, s1, o);
    }
    if (lane == 0) {
        out[(size_t)gw * 2 + 0] = s0 + bd[0];
        out[(size_t)gw * 2 + 1] = s1 + bd[1];
    }
}

// ---------------------------------------------------------------------------
extern "C" void kernel_launch(void* const* d_in, const int* in_sizes, int n_in,
                              void* d_out, int out_size) {
    const int*   inp  = (const int*)  d_in[0];
    const float* h0   = (const float*)d_in[1];
    const float* c0   = (const float*)d_in[2];
    const float* emb  = (const float*)d_in[3];
    const float *W_mx = (const float*)d_in[4],  *b_mx = (const float*)d_in[5];
    const float *W_mh = (const float*)d_in[6],  *b_mh = (const float*)d_in[7];
    const float *W_fx = (const float*)d_in[8],  *b_fx = (const float*)d_in[9];
    const float *W_fm = (const float*)d_in[10], *b_fm = (const float*)d_in[11];
    const float *W_ix = (const float*)d_in[12], *b_ix = (const float*)d_in[13];
    const float *W_im = (const float*)d_in[14], *b_im = (const float*)d_in[15];
    const float *W_ox = (const float*)d_in[16], *b_ox = (const float*)d_in[17];
    const float *W_om = (const float*)d_in[18], *b_om = (const float*)d_in[19];
    const float *W_cx = (const float*)d_in[20], *b_cx = (const float*)d_in[21];
    const float *W_cm = (const float*)d_in[22], *b_cm = (const float*)d_in[23];
    const float *W_dec= (const float*)d_in[24], *b_dec= (const float*)d_in[25];
    float* out = (float*)d_out;

    __nv_bfloat16 *wbf, *h0b;
    uint8_t *w8;
    cudaGetSymbolAddress((void**)&wbf, g_wbf);
    cudaGetSymbolAddress((void**)&h0b, g_h0b);
    cudaGetSymbolAddress((void**)&w8,  g_w8);

    // 1) bf16 conversions
    Cvt5 c5;
    c5.s[0] = W_mx; c5.d[0] = wbf + OFF_MX; c5.n4[0] = 2 * MEG / 4;
    c5.s[1] = W_mh; c5.d[1] = wbf + OFF_MH; c5.n4[1] = 4 * MEG / 4;
    c5.s[2] = W_cx; c5.d[2] = wbf + OFF_CX; c5.n4[2] = 2 * MEG / 4;
    c5.s[3] = W_cm; c5.d[3] = wbf + OFF_CM; c5.n4[3] = 4 * MEG / 4;
    c5.s[4] = h0;   c5.d[4] = h0b;          c5.n4[4] = 16 * MEG / 4;
    cvt_f32_bf16<<<dim3(1024, 5), 256>>>(c5);

    // 2) fp8 conversions (f=0, i=1, o=2)
    Cvt6 c6;
    const float* gs[6] = {W_fx, W_fm, W_ix, W_im, W_ox, W_om};
    for (int z = 0; z < 3; z++) {
        c6.s[2*z]   = gs[2*z];   c6.d[2*z]   = w8 + OFF8_ZX(z); c6.n4[2*z]   = 2 * MEG / 4;
        c6.s[2*z+1] = gs[2*z+1]; c6.d[2*z+1] = w8 + OFF8_ZM(z); c6.n4[2*z+1] = 4 * MEG / 4;
    }
    cvt_f32_fp8<<<dim3(1024, 6), 256>>>(c6);

    // 3) gather
    gather_x<<<B_, 256>>>(inp, emb);

    // 4) m_t
    cudaFuncSetAttribute(gemm_mt, cudaFuncAttributeMaxDynamicSharedMemorySize, BF_SMEM);
    gemm_mt<<<dim3(H_ / 128, B_ / 128), 512, BF_SMEM>>>(b_mx, b_mh);

    // 5) ct (bf16)
    cudaFuncSetAttribute(gemm_c, cudaFuncAttributeMaxDynamicSharedMemorySize, BF_SMEM);
    gemm_c<<<dim3(H_ / 128, B_ / 128), 512, BF_SMEM>>>(b_cx, b_cm);

    // 6) z_o (fp8)
    cudaFuncSetAttribute(gemm_o, cudaFuncAttributeMaxDynamicSharedMemorySize, O_SMEM);
    gemm_o<<<dim3(H_ / 128, B_ / 128), 512, O_SMEM>>>(b_ox, b_om);

    // 7) f,i (fp8) + final combine into d_out
    float* hx_out = out + 2 * (size_t)B_;
    float* cx_out = hx_out + (size_t)B_ * H_;
    cudaFuncSetAttribute(gemm_fi, cudaFuncAttributeMaxDynamicSharedMemorySize, FI_SMEM);
    gemm_fi<<<dim3(H_ / 128, B_ / 128), 512, FI_SMEM>>>(
        b_fx, b_fm, b_ix, b_im, c0, hx_out, cx_out);

    // 8) decoder
    decoder<<<(B_ * 32) / 256, 256>>>(hx_out, W_dec, b_dec, out);
}